// round 13
// baseline (speedup 1.0000x reference)
#include <cuda_runtime.h>

#define BB 64
#define TT 1024
#define NN 48
#define TM1 1023
#define NCHUNK 16
#define TPC 64
#define WST 1032   // ws row stride (words): 1024 data + 8 zero pad, 16B-aligned

// Scratch (device globals — zero-initialized at load; no allocation allowed)
// ws[b][j][t] = exp(yp[b,t,j] - mu_t), t=0..1023; words 1024..1031 stay 0.
__device__ float g_ws[BB * NN * WST];
__device__ float g_partials[BB * NCHUNK]; // point+trans partial sums
__device__ float g_partmu[BB * NCHUNK];   // partial sums of per-row max mu

// ---------------------------------------------------------------------------
// Kernel 1: parallel part. Per (b,t): row max mu, w=exp(yp-mu) stored
// TRANSPOSED as ws[b][j][t] (staged in smem tile -> full-sector STG.128);
// point score; trans score; sum of mu.
// grid (B, NCHUNK), block 256 (8 warps, each warp owns 8 consecutive t)
// ---------------------------------------------------------------------------
__global__ __launch_bounds__(256) void scores_kernel(
    const float* __restrict__ yt, const float* __restrict__ yp,
    const int* __restrict__ spk,
    const float* __restrict__ tr0, const float* __restrict__ tr1,
    const float* __restrict__ tr2)
{
    __shared__ float sT[3 * NN * NN];
    __shared__ float ybuf[8][2][NN];
    __shared__ float stile[8][NN][9];   // per-warp w tile, inner stride 9 (bank-spread)
    __shared__ float swarp[8];
    __shared__ float swarpmu[8];

    const int b = blockIdx.x, ch = blockIdx.y;
    const int tid = threadIdx.x, w = tid >> 5, l = tid & 31;

    for (int i = tid; i < NN * NN; i += 256) {
        sT[i]               = tr0[i];
        sT[NN * NN + i]     = tr1[i];
        sT[2 * NN * NN + i] = tr2[i];
    }

    const int tbase = ch * TPC + w * 8;
    const float* ytb = yt + (size_t)b * TT * NN;
    const float* ypb = yp + (size_t)b * TT * NN;

    // preload l1 = y_true[b, tbase]
    ybuf[w][0][l] = ytb[tbase * NN + l];
    if (l < 16) ybuf[w][0][32 + l] = ytb[tbase * NN + 32 + l];
    __syncthreads();

    float acc = 0.0f;
    float accmu = 0.0f;
    #pragma unroll 1
    for (int tt = 0; tt < 8; tt++) {
        const int t = tbase + tt;
        const int cur = tt & 1, nxt = cur ^ 1;

        // ---- y_pred row: max, w, point ----
        float y1 = ypb[t * NN + l];
        float y2 = (l < 16) ? ypb[t * NN + 32 + l] : -3.0e38f;
        float m = fmaxf(y1, y2);
        m = fmaxf(m, __shfl_xor_sync(0xffffffffu, m, 16));
        m = fmaxf(m, __shfl_xor_sync(0xffffffffu, m, 8));
        m = fmaxf(m, __shfl_xor_sync(0xffffffffu, m, 4));
        m = fmaxf(m, __shfl_xor_sync(0xffffffffu, m, 2));
        m = fmaxf(m, __shfl_xor_sync(0xffffffffu, m, 1));
        accmu += m;

        stile[w][l][tt] = __expf(y1 - m);
        if (l < 16) stile[w][32 + l][tt] = __expf(y2 - m);

        float t1a = ybuf[w][cur][l];
        acc += y1 * t1a;
        if (l < 16) acc += y2 * ybuf[w][cur][32 + l];

        // ---- transition score ----
        if (t < TM1) {
            float l2a = ytb[(t + 1) * NN + l];
            ybuf[w][nxt][l] = l2a;
            float l2b = 0.0f;
            if (l < 16) { l2b = ytb[(t + 1) * NN + 32 + l]; ybuf[w][nxt][32 + l] = l2b; }
            __syncwarp();
            const int k = spk[b * TM1 + t];
            const float* Tk = sT + k * NN * NN;
            float va = 0.0f, vb = 0.0f;
            #pragma unroll 8
            for (int i = 0; i < NN; i++) {
                float a = ybuf[w][cur][i];
                va += a * Tk[i * NN + l];
                if (l < 16) vb += a * Tk[i * NN + 32 + l];
            }
            acc += va * l2a + vb * l2b;
        }
        __syncwarp();
    }
    __syncwarp();

    // ---- tile writeout: lane pairs (2m,2m+1) -> same j, halves 0/1 ----
    // full 32B sectors: consecutive 16B halves from adjacent lanes.
    #pragma unroll
    for (int r = 0; r < 3; r++) {
        const int jj = r * 16 + (l >> 1);
        const int half = l & 1;
        float4 v;
        v.x = stile[w][jj][half * 4 + 0];
        v.y = stile[w][jj][half * 4 + 1];
        v.z = stile[w][jj][half * 4 + 2];
        v.w = stile[w][jj][half * 4 + 3];
        *(float4*)(g_ws + ((size_t)b * NN + jj) * WST + tbase + half * 4) = v;
    }

    // warp reduce then block reduce
    for (int o = 16; o; o >>= 1) acc += __shfl_xor_sync(0xffffffffu, acc, o);
    if (l == 0) { swarp[w] = acc; swarpmu[w] = accmu; }
    __syncthreads();
    if (tid == 0) {
        float s = 0.0f, smu = 0.0f;
        #pragma unroll
        for (int i = 0; i < 8; i++) { s += swarp[i]; smu += swarpmu[i]; }
        g_partials[b * NCHUNK + ch] = s;
        g_partmu[b * NCHUNK + ch]   = smu;
    }
}

// ---------------------------------------------------------------------------
// Kernel 2: forward scan. One CTA per batch, 96 threads (3 warps).
// thread (j = w*16 + l%16, h = l/16) computes i in [h*24, h*24+24) of
// acc_j = sum_i p_i * E[k]_{i,j}. E lives in SMEM transposed (sET[k][j][i],
// row stride 52) -> k-selection is ONE IMAD, zero branches in the loop.
// 4-step groups: 3 unnormalized steps + renorm by p0 on the 4th (exact
// bookkeeping in c). w streamed as one aligned float4 per group via rolling
// q0/q1/q2 pipeline (step weights = q0.y,q0.z,q0.w,q1.x).
// 256 groups = steps t=1..1024; t=1024 is a phantom (w pad = 0, writes the
// dead buffer); its log(p0) is subtracted after the loop.
// ---------------------------------------------------------------------------
__global__ __launch_bounds__(96) void scan_kernel(
    const int* __restrict__ spk,
    const float* __restrict__ tr0, const float* __restrict__ tr1,
    const float* __restrict__ tr2,
    float* __restrict__ out)
{
    __shared__ __align__(16) float sp[2][NN];
    __shared__ __align__(16) int sspk[1032];
    __shared__ __align__(16) float sET[3 * NN * 52];   // E^T, row stride 52

    const int b = blockIdx.x;
    const int tid = threadIdx.x, w = tid >> 5, l = tid & 31;
    const int j = w * 16 + (l & 15);
    const int h = l >> 4;
    const int ibase = h * 24;

    // Fill sET[k][jj][ii] = exp(tr_k[ii*48 + jj])  (coalesced LDG over jj)
    for (int idx = tid; idx < 3 * NN * NN; idx += 96) {
        const int k = idx / (NN * NN), rem = idx % (NN * NN);
        const int ii = rem / NN, jj = rem % NN;
        const float* tr = (k == 0) ? tr0 : ((k == 1) ? tr1 : tr2);
        sET[(k * NN + jj) * 52 + ii] = __expf(tr[ii * NN + jj]);
    }
    for (int i = tid; i < 1032; i += 96) sspk[i] = (i < TM1) ? spk[b * TM1 + i] : 0;

    const float* wsj = g_ws + ((size_t)b * NN + j) * WST;  // this thread's w stream
    const float* myE = sET + j * 52 + ibase;

    float4 q0 = *(const float4*)(wsj);       // words 0..3  (t=0..3)
    float4 q1 = *(const float4*)(wsj + 4);   // words 4..7
    if (h == 0) sp[0][j] = q0.x;             // p(0) = w(t=0)
    float c = 0.0f;
    int4 kq = *(const int4*)&sspk[0];
    __syncthreads();

#define DOT24(EA) { _Pragma("unroll") \
    for (int q = 0; q < 6; q++) { \
        a0 += pr[4*q+0] * EA[4*q+0]; \
        a1 += pr[4*q+1] * EA[4*q+1]; \
        a2 += pr[4*q+2] * EA[4*q+2]; \
        a3 += pr[4*q+3] * EA[4*q+3]; \
    } }

#define DOSTEP(KK, WV, SRC, DST, NORM)                                         \
    {                                                                          \
        float p0 = 0.0f, rinv = 0.0f;                                          \
        if (NORM) {                                                            \
            p0 = sp[SRC][0];                                                   \
            asm("rcp.approx.f32 %0, %1;" : "=f"(rinv) : "f"(p0));              \
        }                                                                      \
        const float* Ec = myE + (KK) * (NN * 52);                              \
        float pr[24], er[24];                                                  \
        _Pragma("unroll")                                                      \
        for (int q = 0; q < 6; q++) {                                          \
            float4 v = *(const float4*)&sp[SRC][ibase + 4*q];                  \
            pr[4*q+0] = v.x; pr[4*q+1] = v.y; pr[4*q+2] = v.z; pr[4*q+3] = v.w;\
            float4 e = *(const float4*)(Ec + 4*q);                             \
            er[4*q+0] = e.x; er[4*q+1] = e.y; er[4*q+2] = e.z; er[4*q+3] = e.w;\
        }                                                                      \
        float a0 = 0.f, a1 = 0.f, a2 = 0.f, a3 = 0.f;                          \
        DOT24(er)                                                              \
        float partial = (a0 + a1) + (a2 + a3);                                 \
        float accj = partial + __shfl_xor_sync(0xffffffffu, partial, 16);      \
        float scale = (NORM) ? ((WV) * rinv) : (WV);                           \
        if (h == 0) sp[DST][j] = accj * scale;                                 \
        if (NORM) c += __logf(p0);                                             \
        __syncthreads();                                                       \
    }

    #pragma unroll 1
    for (int g = 0; g < 256; g++) {
        float4 q2 = *(const float4*)(wsj + 4 * (g + 2));  // quads 2..257; pad words are 0
        int4 kqn = *(const int4*)&sspk[4 * g + 4];        // next group's k (g=255 -> zeros)
        DOSTEP(kq.x, q0.y, 0, 1, 0)
        DOSTEP(kq.y, q0.z, 1, 0, 0)
        DOSTEP(kq.z, q0.w, 0, 1, 0)
        DOSTEP(kq.w, q1.x, 1, 0, 1)
        q0 = q1; q1 = q2; kq = kqn;
    }

    // undo the phantom step's (t=1024) log(p0): it read sp[1][0], still intact.
    c -= __logf(sp[1][0]);

    if (tid == 0) {
        float sum = 0.0f;
        #pragma unroll
        for (int jj = 0; jj < NN; jj++) sum += sp[1][jj];
        float sc = 0.0f, smu = 0.0f;
        #pragma unroll
        for (int i = 0; i < NCHUNK; i++) {
            sc  += g_partials[b * NCHUNK + i];
            smu += g_partmu[b * NCHUNK + i];
        }
        out[b] = smu + c + __logf(sum) - sc;
    }
}

extern "C" void kernel_launch(void* const* d_in, const int* in_sizes, int n_in,
                              void* d_out, int out_size)
{
    const float* yt  = (const float*)d_in[0];
    const float* yp  = (const float*)d_in[1];
    const int*   spk = (const int*)d_in[2];
    const float* t0  = (const float*)d_in[3];
    const float* t1  = (const float*)d_in[4];
    const float* t2  = (const float*)d_in[5];
    float* out = (float*)d_out;

    dim3 g(BB, NCHUNK);
    scores_kernel<<<g, 256>>>(yt, yp, spk, t0, t1, t2);
    scan_kernel<<<BB, 96>>>(spk, t0, t1, t2, out);
}

// round 14
// speedup vs baseline: 1.1515x; 1.1515x over previous
#include <cuda_runtime.h>

#define BB 64
#define TT 1024
#define NN 48
#define TM1 1023
#define NCHUNK 16
#define TPC 64
#define WST 1032   // ws row stride (words): 1024 data + 8 zero pad, 16B-aligned

// Scratch (device globals — zero-initialized at load; no allocation allowed)
// ws[b][j][t] = exp(yp[b,t,j] - mu_t), t=0..1023; words 1024..1031 stay 0.
__device__ float g_ws[BB * NN * WST];
__device__ float g_partials[BB * NCHUNK]; // point+trans partial sums
__device__ float g_partmu[BB * NCHUNK];   // partial sums of per-row max mu

// ---------------------------------------------------------------------------
// Kernel 1: parallel part (identical to R13 — measured good).
// Per (b,t): row max mu, w=exp(yp-mu) stored TRANSPOSED as ws[b][j][t]
// (staged in smem tile -> full-sector STG.128); point score; trans score;
// sum of mu. grid (B, NCHUNK), block 256.
// ---------------------------------------------------------------------------
__global__ __launch_bounds__(256) void scores_kernel(
    const float* __restrict__ yt, const float* __restrict__ yp,
    const int* __restrict__ spk,
    const float* __restrict__ tr0, const float* __restrict__ tr1,
    const float* __restrict__ tr2)
{
    __shared__ float sT[3 * NN * NN];
    __shared__ float ybuf[8][2][NN];
    __shared__ float stile[8][NN][9];   // per-warp w tile, inner stride 9 (bank-spread)
    __shared__ float swarp[8];
    __shared__ float swarpmu[8];

    const int b = blockIdx.x, ch = blockIdx.y;
    const int tid = threadIdx.x, w = tid >> 5, l = tid & 31;

    for (int i = tid; i < NN * NN; i += 256) {
        sT[i]               = tr0[i];
        sT[NN * NN + i]     = tr1[i];
        sT[2 * NN * NN + i] = tr2[i];
    }

    const int tbase = ch * TPC + w * 8;
    const float* ytb = yt + (size_t)b * TT * NN;
    const float* ypb = yp + (size_t)b * TT * NN;

    // preload l1 = y_true[b, tbase]
    ybuf[w][0][l] = ytb[tbase * NN + l];
    if (l < 16) ybuf[w][0][32 + l] = ytb[tbase * NN + 32 + l];
    __syncthreads();

    float acc = 0.0f;
    float accmu = 0.0f;
    #pragma unroll 1
    for (int tt = 0; tt < 8; tt++) {
        const int t = tbase + tt;
        const int cur = tt & 1, nxt = cur ^ 1;

        // ---- y_pred row: max, w, point ----
        float y1 = ypb[t * NN + l];
        float y2 = (l < 16) ? ypb[t * NN + 32 + l] : -3.0e38f;
        float m = fmaxf(y1, y2);
        m = fmaxf(m, __shfl_xor_sync(0xffffffffu, m, 16));
        m = fmaxf(m, __shfl_xor_sync(0xffffffffu, m, 8));
        m = fmaxf(m, __shfl_xor_sync(0xffffffffu, m, 4));
        m = fmaxf(m, __shfl_xor_sync(0xffffffffu, m, 2));
        m = fmaxf(m, __shfl_xor_sync(0xffffffffu, m, 1));
        accmu += m;

        stile[w][l][tt] = __expf(y1 - m);
        if (l < 16) stile[w][32 + l][tt] = __expf(y2 - m);

        float t1a = ybuf[w][cur][l];
        acc += y1 * t1a;
        if (l < 16) acc += y2 * ybuf[w][cur][32 + l];

        // ---- transition score ----
        if (t < TM1) {
            float l2a = ytb[(t + 1) * NN + l];
            ybuf[w][nxt][l] = l2a;
            float l2b = 0.0f;
            if (l < 16) { l2b = ytb[(t + 1) * NN + 32 + l]; ybuf[w][nxt][32 + l] = l2b; }
            __syncwarp();
            const int k = spk[b * TM1 + t];
            const float* Tk = sT + k * NN * NN;
            float va = 0.0f, vb = 0.0f;
            #pragma unroll 8
            for (int i = 0; i < NN; i++) {
                float a = ybuf[w][cur][i];
                va += a * Tk[i * NN + l];
                if (l < 16) vb += a * Tk[i * NN + 32 + l];
            }
            acc += va * l2a + vb * l2b;
        }
        __syncwarp();
    }
    __syncwarp();

    // ---- tile writeout: lane pairs (2m,2m+1) -> same j, halves 0/1 ----
    // full 32B sectors: consecutive 16B halves from adjacent lanes.
    #pragma unroll
    for (int r = 0; r < 3; r++) {
        const int jj = r * 16 + (l >> 1);
        const int half = l & 1;
        float4 v;
        v.x = stile[w][jj][half * 4 + 0];
        v.y = stile[w][jj][half * 4 + 1];
        v.z = stile[w][jj][half * 4 + 2];
        v.w = stile[w][jj][half * 4 + 3];
        *(float4*)(g_ws + ((size_t)b * NN + jj) * WST + tbase + half * 4) = v;
    }

    // warp reduce then block reduce
    for (int o = 16; o; o >>= 1) acc += __shfl_xor_sync(0xffffffffu, acc, o);
    if (l == 0) { swarp[w] = acc; swarpmu[w] = accmu; }
    __syncthreads();
    if (tid == 0) {
        float s = 0.0f, smu = 0.0f;
        #pragma unroll
        for (int i = 0; i < 8; i++) { s += swarp[i]; smu += swarpmu[i]; }
        g_partials[b * NCHUNK + ch] = s;
        g_partmu[b * NCHUNK + ch]   = smu;
    }
}

// ---------------------------------------------------------------------------
// Kernel 2: forward scan — REVERTED to the R6 register-E configuration
// (measured 124us) on the new WST=1032 layout. One CTA per batch, 96 threads.
// thread (j = w*16 + l%16, h = l/16) computes i in [h*24, h*24+24) of
// acc_j = sum_i p_i * E[k]_{i,j}; E columns live in REGISTERS (3-way uniform
// branch on k). 4-step groups: 3 unnormalized steps + renorm by p0 on the
// 4th (exact bookkeeping in c). w streamed as one aligned float4 per group
// via rolling q0/q1/q2 pipeline (step weights = q0.y,q0.z,q0.w,q1.x).
// 256 groups = steps t=1..1024; t=1024 is a phantom (w pad = 0, writes the
// dead buffer); its log(p0) is subtracted after the loop.
// ---------------------------------------------------------------------------
__global__ __launch_bounds__(96) void scan_kernel(
    const int* __restrict__ spk,
    const float* __restrict__ tr0, const float* __restrict__ tr1,
    const float* __restrict__ tr2,
    float* __restrict__ out)
{
    __shared__ __align__(16) float sp[2][NN];
    __shared__ __align__(16) int sspk[1032];

    const int b = blockIdx.x;
    const int tid = threadIdx.x, w = tid >> 5, l = tid & 31;
    const int j = w * 16 + (l & 15);
    const int h = l >> 4;
    const int ibase = h * 24;

    // E columns in registers: E[k][ibase+ii][j]
    float E0[24], E1[24], E2[24];
    #pragma unroll
    for (int ii = 0; ii < 24; ii++) {
        const int idx = (ibase + ii) * NN + j;
        E0[ii] = __expf(tr0[idx]);
        E1[ii] = __expf(tr1[idx]);
        E2[ii] = __expf(tr2[idx]);
    }

    for (int i = tid; i < 1032; i += 96) sspk[i] = (i < TM1) ? spk[b * TM1 + i] : 0;

    const float* wsj = g_ws + ((size_t)b * NN + j) * WST;  // this thread's w stream

    float4 q0 = *(const float4*)(wsj);       // words 0..3  (t=0..3)
    float4 q1 = *(const float4*)(wsj + 4);   // words 4..7
    if (h == 0) sp[0][j] = q0.x;             // p(0) = w(t=0)
    float c = 0.0f;
    int4 kq = *(const int4*)&sspk[0];
    __syncthreads();

#define DOT24(EA) { _Pragma("unroll") \
    for (int q = 0; q < 6; q++) { \
        a0 += pr[4*q+0] * EA[4*q+0]; \
        a1 += pr[4*q+1] * EA[4*q+1]; \
        a2 += pr[4*q+2] * EA[4*q+2]; \
        a3 += pr[4*q+3] * EA[4*q+3]; \
    } }

#define DOSTEP(KK, WV, SRC, DST, NORM)                                         \
    {                                                                          \
        float p0 = 0.0f, rinv = 0.0f;                                          \
        if (NORM) {                                                            \
            p0 = sp[SRC][0];                                                   \
            asm("rcp.approx.f32 %0, %1;" : "=f"(rinv) : "f"(p0));              \
        }                                                                      \
        float pr[24];                                                          \
        _Pragma("unroll")                                                      \
        for (int q = 0; q < 6; q++) {                                          \
            float4 v = *(const float4*)&sp[SRC][ibase + 4*q];                  \
            pr[4*q+0] = v.x; pr[4*q+1] = v.y; pr[4*q+2] = v.z; pr[4*q+3] = v.w;\
        }                                                                      \
        float a0 = 0.f, a1 = 0.f, a2 = 0.f, a3 = 0.f;                          \
        if ((KK) == 0)      DOT24(E0)                                          \
        else if ((KK) == 1) DOT24(E1)                                          \
        else                DOT24(E2)                                          \
        float partial = (a0 + a1) + (a2 + a3);                                 \
        float accj = partial + __shfl_xor_sync(0xffffffffu, partial, 16);      \
        float scale = (NORM) ? ((WV) * rinv) : (WV);                           \
        if (h == 0) sp[DST][j] = accj * scale;                                 \
        if (NORM) c += __logf(p0);                                             \
        __syncthreads();                                                       \
    }

    #pragma unroll 1
    for (int g = 0; g < 256; g++) {
        float4 q2 = *(const float4*)(wsj + 4 * (g + 2));  // quads 2..257; pad words are 0
        int4 kqn = *(const int4*)&sspk[4 * g + 4];        // next group's k (g=255 -> zeros)
        DOSTEP(kq.x, q0.y, 0, 1, 0)
        DOSTEP(kq.y, q0.z, 1, 0, 0)
        DOSTEP(kq.z, q0.w, 0, 1, 0)
        DOSTEP(kq.w, q1.x, 1, 0, 1)
        q0 = q1; q1 = q2; kq = kqn;
    }

    // undo the phantom step's (t=1024) log(p0): it read sp[1][0], still intact.
    c -= __logf(sp[1][0]);

    if (tid == 0) {
        float sum = 0.0f;
        #pragma unroll
        for (int jj = 0; jj < NN; jj++) sum += sp[1][jj];
        float sc = 0.0f, smu = 0.0f;
        #pragma unroll
        for (int i = 0; i < NCHUNK; i++) {
            sc  += g_partials[b * NCHUNK + i];
            smu += g_partmu[b * NCHUNK + i];
        }
        out[b] = smu + c + __logf(sum) - sc;
    }
}

extern "C" void kernel_launch(void* const* d_in, const int* in_sizes, int n_in,
                              void* d_out, int out_size)
{
    const float* yt  = (const float*)d_in[0];
    const float* yp  = (const float*)d_in[1];
    const int*   spk = (const int*)d_in[2];
    const float* t0  = (const float*)d_in[3];
    const float* t1  = (const float*)d_in[4];
    const float* t2  = (const float*)d_in[5];
    float* out = (float*)d_out;

    dim3 g(BB, NCHUNK);
    scores_kernel<<<g, 256>>>(yt, yp, spk, t0, t1, t2);
    scan_kernel<<<BB, 96>>>(spk, t0, t1, t2, out);
}